// round 2
// baseline (speedup 1.0000x reference)
#include <cuda_runtime.h>
#include <math_constants.h>

// Problem constants (fixed by setup_inputs: pcd [8, 4096, 3] f32, k = 5)
#define N_PTS   4096
#define BATCHES 8
#define K_NN    5
#define THREADS 128          // threads per block
#define PTS_PER_BLOCK 256    // each thread handles 2 query points

// ---------------------------------------------------------------------------
// Top-5 sorted insertion (ascending). Strict '<' + ascending j replicates
// jax.lax.top_k's stable lower-index tie-breaking.
// ---------------------------------------------------------------------------
__device__ __forceinline__ void insert5(float d, int j,
                                        float& d0, float& d1, float& d2,
                                        float& d3, float& d4,
                                        int& i0, int& i1, int& i2,
                                        int& i3, int& i4)
{
    if (d < d4) {
        if (d < d3) {
            d4 = d3; i4 = i3;
            if (d < d2) {
                d3 = d2; i3 = i2;
                if (d < d1) {
                    d2 = d1; i2 = i1;
                    if (d < d0) {
                        d1 = d0; i1 = i0;
                        d0 = d;  i0 = j;
                    } else {
                        d1 = d;  i1 = j;
                    }
                } else {
                    d2 = d; i2 = j;
                }
            } else {
                d3 = d; i3 = j;
            }
        } else {
            d4 = d; i4 = j;
        }
    }
}

// Trace of the 3x3 covariance of the 5 neighbors = sum of squared deviations
// from centroid, divided by (k-1) = 4.
__device__ __forceinline__ float trace5(const float4* __restrict__ sh,
                                        int i0, int i1, int i2, int i3, int i4)
{
    float4 n0 = sh[i0], n1 = sh[i1], n2 = sh[i2], n3 = sh[i3], n4 = sh[i4];
    float cx = (n0.x + n1.x + n2.x + n3.x + n4.x) * (1.0f / 5.0f);
    float cy = (n0.y + n1.y + n2.y + n3.y + n4.y) * (1.0f / 5.0f);
    float cz = (n0.z + n1.z + n2.z + n3.z + n4.z) * (1.0f / 5.0f);
    float t = 0.0f;
    float dx, dy, dz;
    dx = n0.x - cx; dy = n0.y - cy; dz = n0.z - cz; t += dx*dx + dy*dy + dz*dz;
    dx = n1.x - cx; dy = n1.y - cy; dz = n1.z - cz; t += dx*dx + dy*dy + dz*dz;
    dx = n2.x - cx; dy = n2.y - cy; dz = n2.z - cz; t += dx*dx + dy*dy + dz*dz;
    dx = n3.x - cx; dy = n3.y - cy; dz = n3.z - cz; t += dx*dx + dy*dy + dz*dz;
    dx = n4.x - cx; dy = n4.y - cy; dz = n4.z - cz; t += dx*dx + dy*dy + dz*dz;
    return t * 0.25f;   // / (k - 1)
}

// ---------------------------------------------------------------------------
// Kernel A: per (batch, 256-point chunk) block. Whole batch point cloud lives
// in shared memory as float4 (x, y, z, |p|^2). Each thread brute-force scans
// all 4096 candidates for 2 query points, keeping top-5 smallest d2 in
// registers, then writes the covariance trace to out[].
// ---------------------------------------------------------------------------
__global__ void __launch_bounds__(THREADS)
knn_trace_kernel(const float* __restrict__ pcd, float* __restrict__ out)
{
    extern __shared__ float4 sh[];          // N_PTS float4 = 64 KB
    const int b = blockIdx.y;
    const float* __restrict__ P = pcd + (size_t)b * N_PTS * 3;

    // Fill shared memory: (x, y, z, x^2+y^2+z^2) per point.
    for (int p = threadIdx.x; p < N_PTS; p += THREADS) {
        float x = P[p * 3 + 0];
        float y = P[p * 3 + 1];
        float z = P[p * 3 + 2];
        float sq = fmaf(z, z, fmaf(y, y, x * x));
        sh[p] = make_float4(x, y, z, sq);
    }
    __syncthreads();

    const int iA = blockIdx.x * PTS_PER_BLOCK + threadIdx.x;
    const int iB = iA + THREADS;

    const float4 a = sh[iA];
    const float4 c = sh[iB];

    float da0 = CUDART_INF_F, da1 = CUDART_INF_F, da2 = CUDART_INF_F,
          da3 = CUDART_INF_F, da4 = CUDART_INF_F;
    int   ja0 = 0, ja1 = 0, ja2 = 0, ja3 = 0, ja4 = 0;
    float db0 = CUDART_INF_F, db1 = CUDART_INF_F, db2 = CUDART_INF_F,
          db3 = CUDART_INF_F, db4 = CUDART_INF_F;
    int   jb0 = 0, jb1 = 0, jb2 = 0, jb3 = 0, jb4 = 0;

    #pragma unroll 8
    for (int j = 0; j < N_PTS; ++j) {
        const float4 q = sh[j];
        // d2 = |a|^2 + |q|^2 - 2 a.q   (same expansion as the reference)
        float dotA = fmaf(a.z, q.z, fmaf(a.y, q.y, a.x * q.x));
        float dA   = fmaf(-2.0f, dotA, a.w + q.w);
        dA = fmaxf(dA, 0.0f);
        insert5(dA, j, da0, da1, da2, da3, da4, ja0, ja1, ja2, ja3, ja4);

        float dotB = fmaf(c.z, q.z, fmaf(c.y, q.y, c.x * q.x));
        float dB   = fmaf(-2.0f, dotB, c.w + q.w);
        dB = fmaxf(dB, 0.0f);
        insert5(dB, j, db0, db1, db2, db3, db4, jb0, jb1, jb2, jb3, jb4);
    }

    out[(size_t)b * N_PTS + iA] = trace5(sh, ja0, ja1, ja2, ja3, ja4);
    out[(size_t)b * N_PTS + iB] = trace5(sh, jb0, jb1, jb2, jb3, jb4);
}

// ---------------------------------------------------------------------------
// Kernel B: per-batch normalization. curvature = trace / (sum(trace) + 1e-8).
// One block per batch; deterministic tree reduction.
// ---------------------------------------------------------------------------
__global__ void __launch_bounds__(256)
normalize_kernel(float* __restrict__ out)
{
    __shared__ float red[8];
    const int b = blockIdx.x;
    float* __restrict__ o = out + (size_t)b * N_PTS;

    float vals[16];
    float s = 0.0f;
    #pragma unroll
    for (int r = 0; r < 16; ++r) {
        vals[r] = o[threadIdx.x + r * 256];
        s += vals[r];
    }
    // Warp reduction
    #pragma unroll
    for (int off = 16; off; off >>= 1)
        s += __shfl_xor_sync(0xFFFFFFFFu, s, off);
    if ((threadIdx.x & 31) == 0)
        red[threadIdx.x >> 5] = s;
    __syncthreads();

    float tot = 0.0f;
    #pragma unroll
    for (int w = 0; w < 8; ++w)
        tot += red[w];

    const float denom = tot + 1e-8f;
    #pragma unroll
    for (int r = 0; r < 16; ++r)
        o[threadIdx.x + r * 256] = vals[r] / denom;
}

// ---------------------------------------------------------------------------
extern "C" void kernel_launch(void* const* d_in, const int* in_sizes, int n_in,
                              void* d_out, int out_size)
{
    const float* pcd = (const float*)d_in[0];
    // d_in[1] is k (always 5 for this problem instance) — compile-time K_NN.
    float* out = (float*)d_out;

    cudaFuncSetAttribute(knn_trace_kernel,
                         cudaFuncAttributeMaxDynamicSharedMemorySize,
                         N_PTS * sizeof(float4));

    dim3 grid(N_PTS / PTS_PER_BLOCK, BATCHES);
    knn_trace_kernel<<<grid, THREADS, N_PTS * sizeof(float4)>>>(pcd, out);
    normalize_kernel<<<BATCHES, 256>>>(out);
}

// round 4
// speedup vs baseline: 4.4632x; 4.4632x over previous
#include <cuda_runtime.h>
#include <math_constants.h>

// pcd [8, 4096, 3] f32, k = 5 (compile-time)
#define N_PTS   4096
#define BATCHES 8
#define THREADS 256
#define QPB     128      // queries per block (2 threads cooperate per query)
#define HALF    2048     // candidates scanned per thread
#define UNROLL  8

// ---------------------------------------------------------------------------
// Main kernel: one block = 128 queries of one batch. Whole batch point cloud
// (x,y,z,|p|^2) lives in shared memory. Threads t and t+128 split the 4096
// candidates; each keeps a sorted top-5 of e = |q|^2 - 2 a.q (same ranking as
// squared distance, constant |a|^2 dropped). Low thread merges, gathers the 5
// neighbor coords from smem, and writes the covariance trace.
// ---------------------------------------------------------------------------
__global__ void __launch_bounds__(THREADS, 2)
knn_trace_kernel(const float* __restrict__ pcd, float* __restrict__ out)
{
    extern __shared__ char smem_raw[];
    float4* sh = reinterpret_cast<float4*>(smem_raw);               // 4096*16 = 64 KB
    float2* mergebuf = reinterpret_cast<float2*>(smem_raw + N_PTS * sizeof(float4)); // 128*5

    const int b = blockIdx.y;
    const float* __restrict__ P = pcd + (size_t)b * N_PTS * 3;

    // Fill shared memory: (x, y, z, |p|^2)
    for (int p = threadIdx.x; p < N_PTS; p += THREADS) {
        float x = P[p * 3 + 0];
        float y = P[p * 3 + 1];
        float z = P[p * 3 + 2];
        sh[p] = make_float4(x, y, z, fmaf(z, z, fmaf(y, y, x * x)));
    }
    __syncthreads();

    const int t    = threadIdx.x & (QPB - 1);     // query lane within block
    const int half = threadIdx.x >> 7;            // 0: candidates [0,2048), 1: [2048,4096)
    const int q    = blockIdx.x * QPB + t;
    const int j0   = half * HALF;

    const float4 a  = sh[q];
    const float  ax = a.x, ay = a.y, az = a.z;

    // Sorted ascending top-5 of e; strict '<' + ascending j reproduces
    // jax.lax.top_k's stable lower-index tie-breaking within each half.
    float e0 = CUDART_INF_F, e1 = CUDART_INF_F, e2 = CUDART_INF_F,
          e3 = CUDART_INF_F, e4 = CUDART_INF_F;
    int   i0 = 0, i1 = 0, i2 = 0, i3 = 0, i4 = 0;

    for (int jj = 0; jj < HALF; jj += UNROLL) {
        // Stage 8 candidates (batched LDS.128, broadcast within warp)
        float4 Q[UNROLL];
        #pragma unroll
        for (int u = 0; u < UNROLL; ++u)
            Q[u] = sh[j0 + jj + u];

        // Uniform math: 8 independent e values
        float ev[UNROLL];
        #pragma unroll
        for (int u = 0; u < UNROLL; ++u) {
            float dot = fmaf(az, Q[u].z, fmaf(ay, Q[u].y, ax * Q[u].x));
            ev[u] = fmaf(-2.0f, dot, Q[u].w);    // |q|^2 - 2 a.q
        }

        // Rare guarded inserts (single-level branch, select-based shift)
        #pragma unroll
        for (int u = 0; u < UNROLL; ++u) {
            const float e = ev[u];
            if (e < e4) {
                const int  j  = j0 + jj + u;
                const bool p3 = e < e3, p2 = e < e2, p1 = e < e1, p0 = e < e0;
                e4 = p3 ? e3 : e;              i4 = p3 ? i3 : j;
                e3 = p3 ? (p2 ? e2 : e) : e3;  i3 = p3 ? (p2 ? i2 : j) : i3;
                e2 = p2 ? (p1 ? e1 : e) : e2;  i2 = p2 ? (p1 ? i1 : j) : i2;
                e1 = p1 ? (p0 ? e0 : e) : e1;  i1 = p1 ? (p0 ? i0 : j) : i1;
                e0 = p0 ? e : e0;              i0 = p0 ? j : i0;
            }
        }
    }

    // High half publishes its sorted 5-list
    if (half == 1) {
        mergebuf[t * 5 + 0] = make_float2(e0, __int_as_float(i0));
        mergebuf[t * 5 + 1] = make_float2(e1, __int_as_float(i1));
        mergebuf[t * 5 + 2] = make_float2(e2, __int_as_float(i2));
        mergebuf[t * 5 + 3] = make_float2(e3, __int_as_float(i3));
        mergebuf[t * 5 + 4] = make_float2(e4, __int_as_float(i4));
    }
    __syncthreads();

    if (half == 0) {
        // Merge my (low-j) list with partner's (high-j) list; on ties the
        // lower index (mine) wins, matching top_k's stable ordering.
        float fe[6] = { e0, e1, e2, e3, e4, CUDART_INF_F };
        int   fi[6] = { i0, i1, i2, i3, i4, 0 };
        float ge[6]; int gi[6];
        #pragma unroll
        for (int s = 0; s < 5; ++s) {
            float2 pr = mergebuf[t * 5 + s];
            ge[s] = pr.x; gi[s] = __float_as_int(pr.y);
        }
        ge[5] = CUDART_INF_F; gi[5] = 0;

        int ia = 0, ib = 0;
        int mi[5];
        #pragma unroll
        for (int s = 0; s < 5; ++s) {
            bool takeA = fe[ia] <= ge[ib];
            mi[s] = takeA ? fi[ia] : gi[ib];
            ia += takeA ? 1 : 0;
            ib += takeA ? 0 : 1;
        }

        // trace(cov) = sum of squared deviations from centroid / (k-1)
        float4 n0 = sh[mi[0]], n1 = sh[mi[1]], n2 = sh[mi[2]],
               n3 = sh[mi[3]], n4 = sh[mi[4]];
        float cx = (n0.x + n1.x + n2.x + n3.x + n4.x) * 0.2f;
        float cy = (n0.y + n1.y + n2.y + n3.y + n4.y) * 0.2f;
        float cz = (n0.z + n1.z + n2.z + n3.z + n4.z) * 0.2f;
        float tr = 0.0f, dx, dy, dz;
        dx = n0.x - cx; dy = n0.y - cy; dz = n0.z - cz; tr += dx*dx + dy*dy + dz*dz;
        dx = n1.x - cx; dy = n1.y - cy; dz = n1.z - cz; tr += dx*dx + dy*dy + dz*dz;
        dx = n2.x - cx; dy = n2.y - cy; dz = n2.z - cz; tr += dx*dx + dy*dy + dz*dz;
        dx = n3.x - cx; dy = n3.y - cy; dz = n3.z - cz; tr += dx*dx + dy*dy + dz*dz;
        dx = n4.x - cx; dy = n4.y - cy; dz = n4.z - cz; tr += dx*dx + dy*dy + dz*dz;

        out[(size_t)b * N_PTS + q] = tr * 0.25f;   // / (k-1)
    }
}

// ---------------------------------------------------------------------------
// Per-batch normalization: curvature = trace / (sum(trace) + 1e-8)
// ---------------------------------------------------------------------------
__global__ void __launch_bounds__(256)
normalize_kernel(float* __restrict__ out)
{
    __shared__ float red[8];
    const int b = blockIdx.x;
    float* __restrict__ o = out + (size_t)b * N_PTS;

    float vals[16];
    float s = 0.0f;
    #pragma unroll
    for (int r = 0; r < 16; ++r) {
        vals[r] = o[threadIdx.x + r * 256];
        s += vals[r];
    }
    #pragma unroll
    for (int off = 16; off; off >>= 1)
        s += __shfl_xor_sync(0xFFFFFFFFu, s, off);
    if ((threadIdx.x & 31) == 0)
        red[threadIdx.x >> 5] = s;
    __syncthreads();

    float tot = 0.0f;
    #pragma unroll
    for (int w = 0; w < 8; ++w)
        tot += red[w];

    const float denom = tot + 1e-8f;
    #pragma unroll
    for (int r = 0; r < 16; ++r)
        o[threadIdx.x + r * 256] = vals[r] / denom;
}

// ---------------------------------------------------------------------------
extern "C" void kernel_launch(void* const* d_in, const int* in_sizes, int n_in,
                              void* d_out, int out_size)
{
    const float* pcd = (const float*)d_in[0];
    float* out = (float*)d_out;

    const int smem = N_PTS * sizeof(float4) + QPB * 5 * sizeof(float2);
    cudaFuncSetAttribute(knn_trace_kernel,
                         cudaFuncAttributeMaxDynamicSharedMemorySize, smem);

    dim3 grid(N_PTS / QPB, BATCHES);   // 32 x 8 = 256 blocks
    knn_trace_kernel<<<grid, THREADS, smem>>>(pcd, out);
    normalize_kernel<<<BATCHES, 256>>>(out);
}

// round 5
// speedup vs baseline: 4.5641x; 1.0226x over previous
#include <cuda_runtime.h>
#include <math_constants.h>

// pcd [8, 4096, 3] f32, k = 5 (compile-time)
#define N_PTS   4096
#define BATCHES 8
#define THREADS 256
#define QPB     128      // queries per block (2 threads per query)
#define HALF    2048     // candidates per thread

typedef unsigned long long ull;

// ---- packed f32x2 helpers (sm_100+) --------------------------------------
__device__ __forceinline__ ull mul2(ull a, ull b) {
    ull r; asm("mul.rn.f32x2 %0,%1,%2;" : "=l"(r) : "l"(a), "l"(b)); return r;
}
__device__ __forceinline__ ull fma2(ull a, ull b, ull c) {
    ull r; asm("fma.rn.f32x2 %0,%1,%2,%3;" : "=l"(r) : "l"(a), "l"(b), "l"(c)); return r;
}
__device__ __forceinline__ ull pack2(float lo, float hi) {
    ull r; asm("mov.b64 %0,{%1,%2};" : "=l"(r) : "f"(lo), "f"(hi)); return r;
}
__device__ __forceinline__ void unpack2(ull v, float& lo, float& hi) {
    asm("mov.b64 {%0,%1},%2;" : "=f"(lo), "=f"(hi) : "l"(v));
}

// Sorted top-5 insert (ascending); strict '<' + ascending j reproduces
// jax.lax.top_k's stable lower-index tie-break.
#define INS(e, j)                                                              \
    if ((e) < le4) {                                                           \
        const bool p3 = (e) < le3, p2 = (e) < le2, p1 = (e) < le1,             \
                   p0 = (e) < le0;                                             \
        le4 = p3 ? le3 : (e);              li4 = p3 ? li3 : (j);               \
        le3 = p3 ? (p2 ? le2 : (e)) : le3; li3 = p3 ? (p2 ? li2 : (j)) : li3;  \
        le2 = p2 ? (p1 ? le1 : (e)) : le2; li2 = p2 ? (p1 ? li1 : (j)) : li2;  \
        le1 = p1 ? (p0 ? le0 : (e)) : le1; li1 = p1 ? (p0 ? li0 : (j)) : li1;  \
        le0 = p0 ? (e) : le0;              li0 = p0 ? (j) : li0;               \
    }

// ---------------------------------------------------------------------------
// Main kernel: one block = 128 queries of one batch. Batch cloud in shared
// memory as SoA (X, Y, Z, W=|p|^2). Threads t and t+128 split the 4096
// candidates; each keeps a sorted top-5 of e = |q|^2 - 2 a.q (same ranking as
// squared distance). Inner loop: double-buffered LDS.128 prefetch + packed
// f32x2 math, guarded scalar inserts. Low thread merges and writes the trace.
// ---------------------------------------------------------------------------
__global__ void __launch_bounds__(THREADS, 2)
knn_trace_kernel(const float* __restrict__ pcd, float* __restrict__ out)
{
    extern __shared__ float smem[];
    float* Xs = smem;
    float* Ys = smem + N_PTS;
    float* Zs = smem + 2 * N_PTS;
    float* Ws = smem + 3 * N_PTS;
    float2* mergebuf = reinterpret_cast<float2*>(smem + 4 * N_PTS); // 128*5

    const int b = blockIdx.y;
    const float* __restrict__ P = pcd + (size_t)b * N_PTS * 3;

    for (int p = threadIdx.x; p < N_PTS; p += THREADS) {
        float x = P[3 * p + 0];
        float y = P[3 * p + 1];
        float z = P[3 * p + 2];
        Xs[p] = x; Ys[p] = y; Zs[p] = z;
        Ws[p] = fmaf(z, z, fmaf(y, y, x * x));
    }
    __syncthreads();

    const int t    = threadIdx.x & (QPB - 1);
    const int half = threadIdx.x >> 7;
    const int q    = blockIdx.x * QPB + t;
    const int j0   = half * HALF;

    const float ax = Xs[q], ay = Ys[q], az = Zs[q];
    const ull ax2 = pack2(ax, ax);
    const ull ay2 = pack2(ay, ay);
    const ull az2 = pack2(az, az);
    const ull m2  = pack2(-2.0f, -2.0f);

    float le0 = CUDART_INF_F, le1 = CUDART_INF_F, le2 = CUDART_INF_F,
          le3 = CUDART_INF_F, le4 = CUDART_INF_F;
    int   li0 = 0, li1 = 0, li2 = 0, li3 = 0, li4 = 0;

    const ulonglong2* X2 = reinterpret_cast<const ulonglong2*>(Xs);
    const ulonglong2* Y2 = reinterpret_cast<const ulonglong2*>(Ys);
    const ulonglong2* Z2 = reinterpret_cast<const ulonglong2*>(Zs);
    const ulonglong2* W2 = reinterpret_cast<const ulonglong2*>(Ws);

    // Preload first 8 candidates (2 x ulonglong2 per component)
    int i4 = j0 >> 2;   // index in 4-float units
    ulonglong2 Ax0 = X2[i4], Ax1 = X2[i4 + 1];
    ulonglong2 Ay0 = Y2[i4], Ay1 = Y2[i4 + 1];
    ulonglong2 Az0 = Z2[i4], Az1 = Z2[i4 + 1];
    ulonglong2 Aw0 = W2[i4], Aw1 = W2[i4 + 1];

    #pragma unroll 2
    for (int jj = 0; jj < HALF; jj += 8) {
        // Prefetch next 8 candidates (reads past the end land in the next
        // SoA array / mergebuf — in-bounds smem, values unused).
        const int n4 = i4 + 2;
        ulonglong2 Bx0 = X2[n4], Bx1 = X2[n4 + 1];
        ulonglong2 By0 = Y2[n4], By1 = Y2[n4 + 1];
        ulonglong2 Bz0 = Z2[n4], Bz1 = Z2[n4 + 1];
        ulonglong2 Bw0 = W2[n4], Bw1 = W2[n4 + 1];

        // Packed math: e = |q|^2 - 2 a.q for 8 candidates (4 f32x2 packs)
        ull t0 = fma2(m2, fma2(az2, Az0.x, fma2(ay2, Ay0.x, mul2(ax2, Ax0.x))), Aw0.x);
        ull t1 = fma2(m2, fma2(az2, Az0.y, fma2(ay2, Ay0.y, mul2(ax2, Ax0.y))), Aw0.y);
        ull t2 = fma2(m2, fma2(az2, Az1.x, fma2(ay2, Ay1.x, mul2(ax2, Ax1.x))), Aw1.x);
        ull t3 = fma2(m2, fma2(az2, Az1.y, fma2(ay2, Ay1.y, mul2(ax2, Ax1.y))), Aw1.y);

        float e0, e1, e2, e3, e4, e5, e6, e7;
        unpack2(t0, e0, e1);
        unpack2(t1, e2, e3);
        unpack2(t2, e4, e5);
        unpack2(t3, e6, e7);

        const int j = j0 + jj;
        INS(e0, j + 0); INS(e1, j + 1); INS(e2, j + 2); INS(e3, j + 3);
        INS(e4, j + 4); INS(e5, j + 5); INS(e6, j + 6); INS(e7, j + 7);

        // Rotate buffers
        Ax0 = Bx0; Ax1 = Bx1; Ay0 = By0; Ay1 = By1;
        Az0 = Bz0; Az1 = Bz1; Aw0 = Bw0; Aw1 = Bw1;
        i4 = n4;
    }

    // High half publishes its sorted 5-list
    if (half == 1) {
        mergebuf[t * 5 + 0] = make_float2(le0, __int_as_float(li0));
        mergebuf[t * 5 + 1] = make_float2(le1, __int_as_float(li1));
        mergebuf[t * 5 + 2] = make_float2(le2, __int_as_float(li2));
        mergebuf[t * 5 + 3] = make_float2(le3, __int_as_float(li3));
        mergebuf[t * 5 + 4] = make_float2(le4, __int_as_float(li4));
    }
    __syncthreads();

    if (half == 0) {
        // Merge low-j list with partner's high-j list; '<=' gives lower index
        // (mine) precedence on ties, matching top_k's stable ordering.
        float fe[6] = { le0, le1, le2, le3, le4, CUDART_INF_F };
        int   fi[6] = { li0, li1, li2, li3, li4, 0 };
        float ge[6]; int gi[6];
        #pragma unroll
        for (int s = 0; s < 5; ++s) {
            float2 pr = mergebuf[t * 5 + s];
            ge[s] = pr.x; gi[s] = __float_as_int(pr.y);
        }
        ge[5] = CUDART_INF_F; gi[5] = 0;

        int ia = 0, ib = 0, mi[5];
        #pragma unroll
        for (int s = 0; s < 5; ++s) {
            bool takeA = fe[ia] <= ge[ib];
            mi[s] = takeA ? fi[ia] : gi[ib];
            ia += takeA ? 1 : 0;
            ib += takeA ? 0 : 1;
        }

        // trace(cov) = sum sq deviations from centroid / (k-1)
        float nx[5], ny[5], nz[5];
        #pragma unroll
        for (int s = 0; s < 5; ++s) {
            nx[s] = Xs[mi[s]]; ny[s] = Ys[mi[s]]; nz[s] = Zs[mi[s]];
        }
        float cx = (nx[0] + nx[1] + nx[2] + nx[3] + nx[4]) * 0.2f;
        float cy = (ny[0] + ny[1] + ny[2] + ny[3] + ny[4]) * 0.2f;
        float cz = (nz[0] + nz[1] + nz[2] + nz[3] + nz[4]) * 0.2f;
        float tr = 0.0f;
        #pragma unroll
        for (int s = 0; s < 5; ++s) {
            float dx = nx[s] - cx, dy = ny[s] - cy, dz = nz[s] - cz;
            tr += dx * dx + dy * dy + dz * dz;
        }
        out[(size_t)b * N_PTS + q] = tr * 0.25f;   // / (k-1)
    }
}

// ---------------------------------------------------------------------------
// Per-batch normalization: curvature = trace / (sum(trace) + 1e-8)
// ---------------------------------------------------------------------------
__global__ void __launch_bounds__(1024)
normalize_kernel(float* __restrict__ out)
{
    __shared__ float red[32];
    const int b = blockIdx.x;
    float* __restrict__ o = out + (size_t)b * N_PTS;

    float vals[4];
    float s = 0.0f;
    #pragma unroll
    for (int r = 0; r < 4; ++r) {
        vals[r] = o[threadIdx.x + r * 1024];
        s += vals[r];
    }
    #pragma unroll
    for (int off = 16; off; off >>= 1)
        s += __shfl_xor_sync(0xFFFFFFFFu, s, off);
    if ((threadIdx.x & 31) == 0)
        red[threadIdx.x >> 5] = s;
    __syncthreads();

    if (threadIdx.x < 32) {
        float v = red[threadIdx.x];
        #pragma unroll
        for (int off = 16; off; off >>= 1)
            v += __shfl_xor_sync(0xFFFFFFFFu, v, off);
        if (threadIdx.x == 0) red[0] = v;
    }
    __syncthreads();

    const float denom = red[0] + 1e-8f;
    #pragma unroll
    for (int r = 0; r < 4; ++r)
        o[threadIdx.x + r * 1024] = vals[r] / denom;
}

// Empty kernel: pads the per-call launch count to 5 so ncu's "-s 5 -c 1"
// (profiles the 6th launch) lands on knn_trace_kernel instead of
// normalize_kernel. Diagnostic aid; ~2-3us cost, removable once tuned.
__global__ void nop_kernel() {}

// ---------------------------------------------------------------------------
extern "C" void kernel_launch(void* const* d_in, const int* in_sizes, int n_in,
                              void* d_out, int out_size)
{
    const float* pcd = (const float*)d_in[0];
    float* out = (float*)d_out;

    const int smem = (4 * N_PTS + QPB * 5 * 2) * sizeof(float);  // 70656 B
    cudaFuncSetAttribute(knn_trace_kernel,
                         cudaFuncAttributeMaxDynamicSharedMemorySize, smem);

    dim3 grid(N_PTS / QPB, BATCHES);   // 32 x 8 = 256 blocks
    knn_trace_kernel<<<grid, THREADS, smem>>>(pcd, out);   // launch 1 (mod 5)
    nop_kernel<<<1, 1>>>();                                // launch 2
    nop_kernel<<<1, 1>>>();                                // launch 3
    nop_kernel<<<1, 1>>>();                                // launch 4
    normalize_kernel<<<BATCHES, 1024>>>(out);              // launch 5
}